// round 2
// baseline (speedup 1.0000x reference)
#include <cuda_runtime.h>

// 32 images * 64 tiles = 2048 tiles; 1024 CTAs x 2 tiles each
#define NUM_CTAS 1024
__device__ float g_partials[NUM_CTAS];
__device__ unsigned int g_done_count = 0;

__device__ __forceinline__ float block_reduce(float acc, float* warp_sums)
{
    #pragma unroll
    for (int off = 16; off > 0; off >>= 1)
        acc += __shfl_xor_sync(0xFFFFFFFFu, acc, off);

    int wid = threadIdx.x >> 5;
    int lid = threadIdx.x & 31;
    if (lid == 0) warp_sums[wid] = acc;
    __syncthreads();

    float v = 0.0f;
    if (wid == 0) {
        v = (lid < 8) ? warp_sums[lid] : 0.0f;
        #pragma unroll
        for (int off = 4; off > 0; off >>= 1)
            v += __shfl_xor_sync(0xFFFFFFFFu, v, off);
    }
    __syncthreads();   // warp_sums reusable afterwards
    return v;          // valid in warp 0 (all lanes), lane0 authoritative
}

// Sum(fake - real) over one 128x128 tile, 256 threads.
__device__ __forceinline__ float tile_sum(const float* __restrict__ fake,
                                          const float* __restrict__ real,
                                          int tile)
{
    const int b   = tile >> 6;             // image (64 tiles per image)
    const int rem = tile & 63;
    const int by  = rem >> 3;
    const int bx  = rem & 7;
    const long base = (long)b * (1024 * 1024) + (long)by * 128 * 1024 + (long)bx * 128;

    const float4* f4 = (const float4*)(fake + base);
    const float4* r4 = (const float4*)(real + base);
    // 128 rows x 32 float4/row; row stride = 256 float4

    float acc = 0.0f;
    #pragma unroll
    for (int it = 0; it < 16; ++it) {
        int i   = threadIdx.x + it * 256;  // 0..4095
        int row = i >> 5;
        int c4  = i & 31;
        float4 fv = f4[row * 256 + c4];
        float4 rv = r4[row * 256 + c4];
        acc += (fv.x - rv.x) + (fv.y - rv.y) + (fv.z - rv.z) + (fv.w - rv.w);
    }
    return acc;
}

__global__ __launch_bounds__(256) void lthu_fused_kernel(
    const float* __restrict__ fake, const float* __restrict__ real,
    float* __restrict__ out)
{
    __shared__ float warp_sums[8];
    __shared__ bool is_last;

    const int blk = blockIdx.x;

    // tile 0: blk, tile 1: blk + 1024
    float s0 = tile_sum(fake, real, blk);
    float r0 = block_reduce(s0, warp_sums);

    float s1 = tile_sum(fake, real, blk + NUM_CTAS);
    float r1 = block_reduce(s1, warp_sums);

    if (threadIdx.x == 0) {
        g_partials[blk] = fabsf(r0) + fabsf(r1);
        __threadfence();
        unsigned int prev = atomicAdd(&g_done_count, 1u);
        is_last = (prev == NUM_CTAS - 1);
    }
    __syncthreads();

    if (is_last) {
        // fixed-order deterministic reduce of 1024 partials
        float acc = 0.0f;
        #pragma unroll
        for (int it = 0; it < 4; ++it)
            acc += g_partials[threadIdx.x + it * 256];

        float total = block_reduce(acc, warp_sums);
        if (threadIdx.x == 0) {
            out[0] = total * (1.0f / (16384.0f * 32.0f));
            g_done_count = 0;   // reset for next (graph-replayed) call
        }
    }
}

extern "C" void kernel_launch(void* const* d_in, const int* in_sizes, int n_in,
                              void* d_out, int out_size)
{
    const float* fake = (const float*)d_in[0];
    const float* real = (const float*)d_in[1];
    float* out = (float*)d_out;

    lthu_fused_kernel<<<NUM_CTAS, 256>>>(fake, real, out);
}

// round 3
// speedup vs baseline: 1.2346x; 1.2346x over previous
#include <cuda_runtime.h>

// 32 images * 64 tiles = 2048 tiles; one CTA per tile
#define NUM_TILES 2048
__device__ float g_partials[NUM_TILES];
__device__ unsigned int g_done_count = 0;

__device__ __forceinline__ float block_reduce(float acc, float* warp_sums)
{
    #pragma unroll
    for (int off = 16; off > 0; off >>= 1)
        acc += __shfl_xor_sync(0xFFFFFFFFu, acc, off);

    int wid = threadIdx.x >> 5;
    int lid = threadIdx.x & 31;
    if (lid == 0) warp_sums[wid] = acc;
    __syncthreads();

    float v = 0.0f;
    if (wid == 0) {
        v = (lid < 8) ? warp_sums[lid] : 0.0f;
        #pragma unroll
        for (int off = 4; off > 0; off >>= 1)
            v += __shfl_xor_sync(0xFFFFFFFFu, v, off);
    }
    return v;   // lane 0 of warp 0 authoritative
}

__global__ __launch_bounds__(256) void lthu_kernel(
    const float* __restrict__ fake, const float* __restrict__ real,
    float* __restrict__ out)
{
    __shared__ float warp_sums[8];
    __shared__ bool is_last;

    const int blk = blockIdx.x;            // 0..2047, one tile each
    const int b   = blk >> 6;              // image (64 tiles per image)
    const int rem = blk & 63;
    const int by  = rem >> 3;
    const int bx  = rem & 7;
    const long base = (long)b * (1024 * 1024) + (long)by * 128 * 1024 + (long)bx * 128;

    const float4* f4 = (const float4*)(fake + base);
    const float4* r4 = (const float4*)(real + base);
    // tile: 128 rows x 32 float4/row; row stride in float4 = 256

    float acc = 0.0f;
    #pragma unroll
    for (int it = 0; it < 16; ++it) {
        int i   = threadIdx.x + it * 256;  // 0..4095
        int row = i >> 5;
        int c4  = i & 31;
        float4 fv = f4[row * 256 + c4];
        float4 rv = r4[row * 256 + c4];
        acc += (fv.x - rv.x) + (fv.y - rv.y) + (fv.z - rv.z) + (fv.w - rv.w);
    }

    float tile_total = block_reduce(acc, warp_sums);

    if (threadIdx.x == 0) {
        g_partials[blk] = fabsf(tile_total);
        __threadfence();
        unsigned int prev = atomicAdd(&g_done_count, 1u);
        is_last = (prev == NUM_TILES - 1);
    }
    __syncthreads();

    if (is_last) {
        // fixed-order deterministic reduce of 2048 partials
        float s = 0.0f;
        #pragma unroll
        for (int it = 0; it < 8; ++it)
            s += g_partials[threadIdx.x + it * 256];

        float total = block_reduce(s, warp_sums);
        if (threadIdx.x == 0) {
            out[0] = total * (1.0f / (16384.0f * 32.0f));
            g_done_count = 0;   // reset for next graph replay
        }
    }
}

extern "C" void kernel_launch(void* const* d_in, const int* in_sizes, int n_in,
                              void* d_out, int out_size)
{
    const float* fake = (const float*)d_in[0];
    const float* real = (const float*)d_in[1];
    float* out = (float*)d_out;

    lthu_kernel<<<NUM_TILES, 256>>>(fake, real, out);
}